// round 6
// baseline (speedup 1.0000x reference)
#include <cuda_runtime.h>
#include <cuda_bf16.h>
#include <cstddef>

// score(f) = 1 + tanh(f.W + b)/10 ; e[parent] = score(c0)*e[c0] + score(c1)*e[c1]
// Complete binary tree, level order, D=21, N = 2^21 - 1, F = 64.
// One persistent kernel; 32-child warp tiles; folding butterfly reduction.

#define TANH_INV_SCALAR 0.1f
#define NB       296         // 2 blocks/SM on 148 SMs -> all resident
#define NTHREADS 256
#define NWARPS   (NB * (NTHREADS / 32))

__device__ unsigned g_count = 0;
__device__ volatile unsigned g_gen = 0;

__device__ __forceinline__ void grid_barrier()
{
    __syncthreads();
    if (threadIdx.x == 0) {
        __threadfence();
        unsigned g = g_gen;
        if (atomicAdd(&g_count, 1u) == NB - 1u) {
            g_count = 0;
            __threadfence();
            g_gen = g + 1u;
        } else {
            while (g_gen == g) { __nanosleep(32); }
            __threadfence();
        }
    }
    __syncthreads();
}

__device__ __forceinline__ float tanh_fast(float x)
{
    float y;
    asm("tanh.approx.f32 %0, %1;" : "=f"(y) : "f"(x));
    return y;
}

__global__ void __launch_bounds__(NTHREADS, 2)
tree_all_kernel(const float* __restrict__ features,
                const float* __restrict__ leaf_energy,
                const float* __restrict__ W,
                const float* __restrict__ bptr,
                float* __restrict__ energy)
{
    const int tid   = threadIdx.x;
    const int lane  = tid & 31;
    const int gwarp = (blockIdx.x * NTHREADS + tid) >> 5;

    const float4 wv = reinterpret_cast<const float4*>(W)[lane & 15];
    const float  b  = __ldg(bptr);

    const bool b3 = lane & 8, b2 = lane & 4, b1 = lane & 2, b0 = lane & 1;
    const int  h  = lane >> 4;                       // sibling half
    // bit-reversed value index this lane ends up holding after the folds
    const int  vi = ((lane & 1) << 3) | ((lane & 2) << 1)
                  | ((lane & 4) >> 1) | ((lane & 8) >> 3);

    const int NLEAF = 1 << 20;
    const int leaf_start = NLEAF - 1;

    // ---- Levels d = 20 .. 5 : warp-tiles of 32 children (8 KB) ----
    for (int d = 20; d >= 5; --d) {
        const int nc     = 1 << d;
        const int cstart = nc - 1;
        const int pstart = (nc >> 1) - 1;
        const int ntiles = nc >> 5;
        const bool leaf_level = (d == 20);

        for (int tile = gwarp; tile < ntiles; tile += NWARPS) {
            const int cbase = cstart + tile * 32;
            const float4* g = reinterpret_cast<const float4*>(
                features + (size_t)cbase * 64);

            // 16 independent coalesced float4 loads (front-batched -> high MLP)
            float4 v[16];
            #pragma unroll
            for (int j = 0; j < 16; ++j)
                v[j] = __ldg(&g[j * 32 + lane]);

            float part[16];
            #pragma unroll
            for (int j = 0; j < 16; ++j)
                part[j] = v[j].x * wv.x + v[j].y * wv.y
                        + v[j].z * wv.z + v[j].w * wv.w;

            // Folding butterfly within each 16-lane half (offsets 8,4,2,1).
            float a8[8];
            #pragma unroll
            for (int j = 0; j < 8; ++j) {
                float u0 = part[2*j]   + __shfl_xor_sync(~0u, part[2*j],   8);
                float u1 = part[2*j+1] + __shfl_xor_sync(~0u, part[2*j+1], 8);
                a8[j] = b3 ? u1 : u0;
            }
            float a4[4];
            #pragma unroll
            for (int j = 0; j < 4; ++j) {
                float u0 = a8[2*j]   + __shfl_xor_sync(~0u, a8[2*j],   4);
                float u1 = a8[2*j+1] + __shfl_xor_sync(~0u, a8[2*j+1], 4);
                a4[j] = b2 ? u1 : u0;
            }
            float a2[2];
            #pragma unroll
            for (int j = 0; j < 2; ++j) {
                float u0 = a4[2*j]   + __shfl_xor_sync(~0u, a4[2*j],   2);
                float u1 = a4[2*j+1] + __shfl_xor_sync(~0u, a4[2*j+1], 2);
                a2[j] = b1 ? u1 : u0;
            }
            float u0 = a2[0] + __shfl_xor_sync(~0u, a2[0], 1);
            float u1 = a2[1] + __shfl_xor_sync(~0u, a2[1], 1);
            float dot = b0 ? u1 : u0;
            // lane holds full dot of row r = 2*vi + h

            const int r  = 2 * vi + h;
            const int ci = cbase + r;

            float e;
            if (leaf_level) {
                e = __ldg(&leaf_energy[ci - leaf_start]);
                __stcg(&energy[ci], e);          // seed output leaves inline
            } else {
                e = __ldcg(&energy[ci]);
            }

            float s = 1.0f + tanh_fast(dot + b) * TANH_INV_SCALAR;
            float contrib = s * e;
            float other = __shfl_xor_sync(~0u, contrib, 16);   // sibling lane
            if (h == 0)
                __stcg(&energy[pstart + tile * 16 + vi], contrib + other);
        }
        grid_barrier();
    }

    // ---- Levels d = 4 .. 1 (nc = 16, 8, 4, 2): single warp ----
    for (int d = 4; d >= 1; --d) {
        const int nc     = 1 << d;
        const int cstart = nc - 1;
        const int pstart = (nc >> 1) - 1;
        if (blockIdx.x == 0 && tid < 32) {
            float contrib = 0.0f;
            if (lane < nc) {
                const int ch = cstart + lane;
                const float* f = features + (size_t)ch * 64;
                float dot = 0.0f;
                #pragma unroll
                for (int k = 0; k < 64; ++k)
                    dot += __ldg(&f[k]) * __ldg(&W[k]);
                float s = 1.0f + tanh_fast(dot + b) * TANH_INV_SCALAR;
                contrib = s * __ldcg(&energy[ch]);
            }
            float other = __shfl_xor_sync(~0u, contrib, 1);
            if (lane < nc && (lane & 1) == 0)
                __stcg(&energy[pstart + (lane >> 1)], contrib + other);
        }
        grid_barrier();
    }
}

extern "C" void kernel_launch(void* const* d_in, const int* in_sizes, int n_in,
                              void* d_out, int out_size)
{
    const float* features    = (const float*)d_in[0];   // [N, 64]
    const float* leaf_energy = (const float*)d_in[1];   // [2^20]
    const float* W           = (const float*)d_in[2];   // [64]
    const float* bptr        = (const float*)d_in[3];   // [1]
    float* energy = (float*)d_out;                      // [N]

    tree_all_kernel<<<NB, NTHREADS>>>(features, leaf_energy, W, bptr, energy);
}

// round 7
// speedup vs baseline: 1.2164x; 1.2164x over previous
#include <cuda_runtime.h>
#include <cuda_bf16.h>
#include <cstddef>

// score(f) = 1 + tanh(f.W + b)/10 ; e[parent] = score(c0)*e[c0] + score(c1)*e[c1]
// Complete binary tree, level order, D=21, N = 2^21 - 1, F = 64.
// One persistent kernel; 16-child warp tiles; folding butterfly; energy prefetch;
// single-block tail for levels d <= 10 (no grid barriers there).

#define TANH_INV_SCALAR 0.1f
#define NB       296         // 2 blocks/SM on 148 SMs -> all resident
#define NTHREADS 256
#define NWARPS   (NB * (NTHREADS / 32))

__device__ unsigned g_count = 0;
__device__ volatile unsigned g_gen = 0;

__device__ __forceinline__ void grid_barrier()
{
    __syncthreads();
    if (threadIdx.x == 0) {
        __threadfence();
        unsigned g = g_gen;
        if (atomicAdd(&g_count, 1u) == NB - 1u) {
            g_count = 0;
            __threadfence();
            g_gen = g + 1u;
        } else {
            while (g_gen == g) { __nanosleep(32); }
            __threadfence();
        }
    }
    __syncthreads();
}

__device__ __forceinline__ float tanh_fast(float x)
{
    float y;
    asm("tanh.approx.f32 %0, %1;" : "=f"(y) : "f"(x));
    return y;
}

// Process one 16-child tile with one warp. Lane layout:
//   col = lane & 15 (fixed W slice), h = lane >> 4 (sibling half)
//   After the fold, each lane holds the full dot of row r = 2*vi + h,
//   vi = bit-reverse3(lane bits 1..3). Lanes paired by bit0 are duplicates.
__device__ __forceinline__ void do_tile(
    const float* __restrict__ features,
    const float* __restrict__ leaf_energy,
    float* __restrict__ energy,
    float4 wv, float b,
    int cstart, int pstart, int tile, int lane,
    bool leaf_level, int leaf_start)
{
    const int cbase = cstart + tile * 16;
    const bool s3 = lane & 8, s2 = lane & 4, s1 = lane & 2;
    const int  h  = lane >> 4;
    const int  vi = ((lane >> 3) & 1) | (((lane >> 2) & 1) << 1)
                  | (((lane >> 1) & 1) << 2);
    const int  r  = 2 * vi + h;
    const int  ci = cbase + r;

    // Prefetch the energy operand FIRST (independent of the dot product).
    float e;
    if (leaf_level) e = __ldg(&leaf_energy[ci - leaf_start]);
    else            e = __ldcg(&energy[ci]);

    // 8 independent coalesced float4 loads (4 KB tile).
    const float4* g = reinterpret_cast<const float4*>(features + (size_t)cbase * 64);
    float part[8];
    #pragma unroll
    for (int j = 0; j < 8; ++j) {
        float4 v = __ldg(&g[j * 32 + lane]);
        part[j] = v.x * wv.x + v.y * wv.y + v.z * wv.z + v.w * wv.w;
    }

    // Folding butterfly: 15 shuffles, every lane ends with one full dot.
    float a4[4];
    #pragma unroll
    for (int j = 0; j < 4; ++j) {
        float u0 = part[2*j]   + __shfl_xor_sync(~0u, part[2*j],   8);
        float u1 = part[2*j+1] + __shfl_xor_sync(~0u, part[2*j+1], 8);
        a4[j] = s3 ? u1 : u0;
    }
    float a2[2];
    #pragma unroll
    for (int j = 0; j < 2; ++j) {
        float u0 = a4[2*j]   + __shfl_xor_sync(~0u, a4[2*j],   4);
        float u1 = a4[2*j+1] + __shfl_xor_sync(~0u, a4[2*j+1], 4);
        a2[j] = s2 ? u1 : u0;
    }
    float u0 = a2[0] + __shfl_xor_sync(~0u, a2[0], 2);
    float u1 = a2[1] + __shfl_xor_sync(~0u, a2[1], 2);
    float a1 = s1 ? u1 : u0;
    float dot = a1 + __shfl_xor_sync(~0u, a1, 1);

    if (leaf_level && (lane & 1) == 0)
        __stcg(&energy[ci], e);                  // seed output leaves inline

    float s = 1.0f + tanh_fast(dot + b) * TANH_INV_SCALAR;
    float contrib = s * e;
    float other = __shfl_xor_sync(~0u, contrib, 16);  // sibling (other h)
    if (h == 0 && (lane & 1) == 0)
        __stcg(&energy[pstart + tile * 8 + vi], contrib + other);
}

__global__ void __launch_bounds__(NTHREADS, 2)
tree_all_kernel(const float* __restrict__ features,
                const float* __restrict__ leaf_energy,
                const float* __restrict__ W,
                const float* __restrict__ bptr,
                float* __restrict__ energy)
{
    const int tid   = threadIdx.x;
    const int lane  = tid & 31;
    const int gwarp = (blockIdx.x * NTHREADS + tid) >> 5;

    const float4 wv = reinterpret_cast<const float4*>(W)[lane & 15];
    const float  b  = __ldg(bptr);

    const int NLEAF = 1 << 20;
    const int leaf_start = NLEAF - 1;

    // ---- Grid-wide levels d = 20 .. 11 ----
    for (int d = 20; d >= 11; --d) {
        const int nc     = 1 << d;
        const int cstart = nc - 1;
        const int pstart = (nc >> 1) - 1;
        const int ntiles = nc >> 4;
        const bool leaf_level = (d == 20);

        for (int tile = gwarp; tile < ntiles; tile += NWARPS)
            do_tile(features, leaf_energy, energy, wv, b,
                    cstart, pstart, tile, lane, leaf_level, leaf_start);
        grid_barrier();
    }

    // ---- Single-block tail: levels d = 10 .. 1 ----
    if (blockIdx.x != 0) return;
    const int bwarp = tid >> 5;

    for (int d = 10; d >= 5; --d) {
        const int nc     = 1 << d;
        const int cstart = nc - 1;
        const int pstart = (nc >> 1) - 1;
        const int ntiles = nc >> 4;
        for (int tile = bwarp; tile < ntiles; tile += NTHREADS / 32)
            do_tile(features, leaf_energy, energy, wv, b,
                    cstart, pstart, tile, lane, false, leaf_start);
        __syncthreads();
    }

    for (int d = 4; d >= 1; --d) {
        const int nc     = 1 << d;
        const int cstart = nc - 1;
        const int pstart = (nc >> 1) - 1;
        if (tid < 32) {
            float contrib = 0.0f;
            if (lane < nc) {
                const int ch = cstart + lane;
                const float* f = features + (size_t)ch * 64;
                float dot = 0.0f;
                #pragma unroll
                for (int k = 0; k < 64; ++k)
                    dot += __ldg(&f[k]) * __ldg(&W[k]);
                float s = 1.0f + tanh_fast(dot + b) * TANH_INV_SCALAR;
                contrib = s * __ldcg(&energy[ch]);
            }
            float other = __shfl_xor_sync(~0u, contrib, 1);
            if (lane < nc && (lane & 1) == 0)
                __stcg(&energy[pstart + (lane >> 1)], contrib + other);
        }
        __syncthreads();
    }
}

extern "C" void kernel_launch(void* const* d_in, const int* in_sizes, int n_in,
                              void* d_out, int out_size)
{
    const float* features    = (const float*)d_in[0];   // [N, 64]
    const float* leaf_energy = (const float*)d_in[1];   // [2^20]
    const float* W           = (const float*)d_in[2];   // [64]
    const float* bptr        = (const float*)d_in[3];   // [1]
    float* energy = (float*)d_out;                      // [N]

    tree_all_kernel<<<NB, NTHREADS>>>(features, leaf_energy, W, bptr, energy);
}

// round 8
// speedup vs baseline: 1.2353x; 1.0156x over previous
#include <cuda_runtime.h>
#include <cuda_bf16.h>
#include <cstddef>

// score(f) = 1 + tanh(f.W + b)/10 ; e[parent] = score(c0)*e[c0] + score(c1)*e[c1]
// Complete binary tree, level order, D=21, N = 2^21 - 1, F = 64.
// One persistent kernel; 16-child warp tiles; folding butterfly;
// depth-2 software pipeline across tiles (next tile's loads in flight
// during current tile's reduction); single-block tail for d <= 10.

#define TANH_INV_SCALAR 0.1f
#define NB       296         // 2 blocks/SM on 148 SMs -> all resident
#define NTHREADS 256
#define NWARPS   (NB * (NTHREADS / 32))

__device__ unsigned g_count = 0;
__device__ volatile unsigned g_gen = 0;

__device__ __forceinline__ void grid_barrier()
{
    __syncthreads();
    if (threadIdx.x == 0) {
        __threadfence();
        unsigned g = g_gen;
        if (atomicAdd(&g_count, 1u) == NB - 1u) {
            g_count = 0;
            __threadfence();
            g_gen = g + 1u;
        } else {
            while (g_gen == g) { __nanosleep(32); }
            __threadfence();
        }
    }
    __syncthreads();
}

__device__ __forceinline__ float tanh_fast(float x)
{
    float y;
    asm("tanh.approx.f32 %0, %1;" : "=f"(y) : "f"(x));
    return y;
}

// Issue all global loads for one 16-child tile (8 float4 features + energy).
__device__ __forceinline__ void tile_load(
    const float* __restrict__ features,
    const float* __restrict__ leaf_energy,
    const float* __restrict__ energy,
    int cstart, int tile, int lane, int r,
    bool leaf_level, int leaf_start,
    float4 v[8], float& e)
{
    const int cbase = cstart + tile * 16;
    const int ci = cbase + r;
    if (leaf_level) e = __ldg(&leaf_energy[ci - leaf_start]);
    else            e = __ldcg(&energy[ci]);
    const float4* g = reinterpret_cast<const float4*>(features + (size_t)cbase * 64);
    #pragma unroll
    for (int j = 0; j < 8; ++j)
        v[j] = __ldg(&g[j * 32 + lane]);
}

// Consume one tile: butterfly-reduce, score, combine siblings, store parent.
__device__ __forceinline__ void tile_compute(
    float* __restrict__ energy,
    const float4 v[8], float e,
    float4 wv, float b,
    int cstart, int pstart, int tile, int lane, int r, int vi,
    bool leaf_level)
{
    const bool s3 = lane & 8, s2 = lane & 4, s1 = lane & 2;
    const int  h  = lane >> 4;

    float part[8];
    #pragma unroll
    for (int j = 0; j < 8; ++j)
        part[j] = v[j].x * wv.x + v[j].y * wv.y + v[j].z * wv.z + v[j].w * wv.w;

    // Folding butterfly: 15 shuffles; every lane ends with one full row dot.
    float a4[4];
    #pragma unroll
    for (int j = 0; j < 4; ++j) {
        float u0 = part[2*j]   + __shfl_xor_sync(~0u, part[2*j],   8);
        float u1 = part[2*j+1] + __shfl_xor_sync(~0u, part[2*j+1], 8);
        a4[j] = s3 ? u1 : u0;
    }
    float a2[2];
    #pragma unroll
    for (int j = 0; j < 2; ++j) {
        float u0 = a4[2*j]   + __shfl_xor_sync(~0u, a4[2*j],   4);
        float u1 = a4[2*j+1] + __shfl_xor_sync(~0u, a4[2*j+1], 4);
        a2[j] = s2 ? u1 : u0;
    }
    float u0 = a2[0] + __shfl_xor_sync(~0u, a2[0], 2);
    float u1 = a2[1] + __shfl_xor_sync(~0u, a2[1], 2);
    float a1 = s1 ? u1 : u0;
    float dot = a1 + __shfl_xor_sync(~0u, a1, 1);

    if (leaf_level && (lane & 1) == 0)
        __stcg(&energy[cstart + tile * 16 + r], e);   // seed output leaves

    float s = 1.0f + tanh_fast(dot + b) * TANH_INV_SCALAR;
    float contrib = s * e;
    float other = __shfl_xor_sync(~0u, contrib, 16);  // sibling half
    if (h == 0 && (lane & 1) == 0)
        __stcg(&energy[pstart + tile * 8 + vi], contrib + other);
}

__global__ void __launch_bounds__(NTHREADS, 2)
tree_all_kernel(const float* __restrict__ features,
                const float* __restrict__ leaf_energy,
                const float* __restrict__ W,
                const float* __restrict__ bptr,
                float* __restrict__ energy)
{
    const int tid   = threadIdx.x;
    const int lane  = tid & 31;
    const int gwarp = (blockIdx.x * NTHREADS + tid) >> 5;

    const float4 wv = reinterpret_cast<const float4*>(W)[lane & 15];
    const float  b  = __ldg(bptr);

    const int h  = lane >> 4;
    const int vi = ((lane >> 3) & 1) | (((lane >> 2) & 1) << 1)
                 | (((lane >> 1) & 1) << 2);
    const int r  = 2 * vi + h;

    const int NLEAF = 1 << 20;
    const int leaf_start = NLEAF - 1;

    // ---- Grid-wide levels d = 20 .. 11, depth-2 pipelined tile loop ----
    for (int d = 20; d >= 11; --d) {
        const int nc     = 1 << d;
        const int cstart = nc - 1;
        const int pstart = (nc >> 1) - 1;
        const int ntiles = nc >> 4;
        const bool leaf_level = (d == 20);

        int tile = gwarp;
        float4 v[8]; float e;
        if (tile < ntiles)
            tile_load(features, leaf_energy, energy, cstart, tile, lane, r,
                      leaf_level, leaf_start, v, e);
        while (tile < ntiles) {
            const int nt = tile + NWARPS;
            float4 nv[8]; float ne = 0.0f;
            if (nt < ntiles)
                tile_load(features, leaf_energy, energy, cstart, nt, lane, r,
                          leaf_level, leaf_start, nv, ne);
            tile_compute(energy, v, e, wv, b,
                         cstart, pstart, tile, lane, r, vi, leaf_level);
            #pragma unroll
            for (int j = 0; j < 8; ++j) v[j] = nv[j];
            e = ne;
            tile = nt;
        }
        grid_barrier();
    }

    // ---- Single-block tail: levels d = 10 .. 1 ----
    if (blockIdx.x != 0) return;
    const int bwarp = tid >> 5;

    for (int d = 10; d >= 5; --d) {
        const int nc     = 1 << d;
        const int cstart = nc - 1;
        const int pstart = (nc >> 1) - 1;
        const int ntiles = nc >> 4;
        for (int tile = bwarp; tile < ntiles; tile += NTHREADS / 32) {
            float4 v[8]; float e;
            tile_load(features, leaf_energy, energy, cstart, tile, lane, r,
                      false, leaf_start, v, e);
            tile_compute(energy, v, e, wv, b,
                         cstart, pstart, tile, lane, r, vi, false);
        }
        __syncthreads();
    }

    for (int d = 4; d >= 1; --d) {
        const int nc     = 1 << d;
        const int cstart = nc - 1;
        const int pstart = (nc >> 1) - 1;
        if (tid < 32) {
            float contrib = 0.0f;
            if (lane < nc) {
                const int ch = cstart + lane;
                const float* f = features + (size_t)ch * 64;
                float dot = 0.0f;
                #pragma unroll
                for (int k = 0; k < 64; ++k)
                    dot += __ldg(&f[k]) * __ldg(&W[k]);
                float s = 1.0f + tanh_fast(dot + b) * TANH_INV_SCALAR;
                contrib = s * __ldcg(&energy[ch]);
            }
            float other = __shfl_xor_sync(~0u, contrib, 1);
            if (lane < nc && (lane & 1) == 0)
                __stcg(&energy[pstart + (lane >> 1)], contrib + other);
        }
        __syncthreads();
    }
}

extern "C" void kernel_launch(void* const* d_in, const int* in_sizes, int n_in,
                              void* d_out, int out_size)
{
    const float* features    = (const float*)d_in[0];   // [N, 64]
    const float* leaf_energy = (const float*)d_in[1];   // [2^20]
    const float* W           = (const float*)d_in[2];   // [64]
    const float* bptr        = (const float*)d_in[3];   // [1]
    float* energy = (float*)d_out;                      // [N]

    tree_all_kernel<<<NB, NTHREADS>>>(features, leaf_energy, W, bptr, energy);
}